// round 8
// baseline (speedup 1.0000x reference)
#include <cuda_runtime.h>

// QuantumCircuitLayer — fused kernel, f32x2 packed arithmetic (sm_103a).
// The two rows each thread handles are the two lanes of every f32x2 op:
// all FMA-pipe work (rotations, entangle, |.|^2) issues at half the
// instruction count of the scalar version. Params are precomputed by the
// first 72 threads of each block into smem as DUPLICATED float2 pairs so
// every parameter use is one broadcast ld.shared.b64.

#define PI_HALF 1.57079632679489662f

typedef unsigned long long u64;

__device__ __forceinline__ u64 pk2(float a, float b) {
    u64 r; asm("mov.b64 %0, {%1, %2};" : "=l"(r) : "f"(a), "f"(b)); return r;
}
__device__ __forceinline__ void upk2(float& a, float& b, u64 v) {
    asm("mov.b64 {%0, %1}, %2;" : "=f"(a), "=f"(b) : "l"(v));
}
__device__ __forceinline__ u64 fma2(u64 a, u64 b, u64 c) {
    u64 d; asm("fma.rn.f32x2 %0, %1, %2, %3;" : "=l"(d) : "l"(a), "l"(b), "l"(c)); return d;
}
__device__ __forceinline__ u64 mul2(u64 a, u64 b) {
    u64 d; asm("mul.rn.f32x2 %0, %1, %2;" : "=l"(d) : "l"(a), "l"(b)); return d;
}
__device__ __forceinline__ float fsqrt_approx(float x) {
    float y; asm("sqrt.approx.f32 %0, %1;" : "=f"(y) : "f"(x)); return y;
}

// smem packed-param layout (each entry = duplicated pair):
//  [ 0.. 5]  -th0[q]   = -0.5*rot[0,q,0]   (layer-0 rotation folded into phase)
//  [ 6..11]   c1[q]     [12..17]  s1[q]    [18..23] -s1[q]
//  [24..29]   c2[q]     [30..35]  s2[q]    [36..41] -s2[q]
//  [42..56]   t[l,j]   = 0.5*sigmoid(ent[l,j])
//  [57..71]   1-t[l,j]
#define P_NTH 0
#define P_C1  6
#define P_S1  12
#define P_S1N 18
#define P_C2  24
#define P_S2  30
#define P_S2N 36
#define P_T   42
#define P_OMT 57

__global__ void __launch_bounds__(256, 6)
qc_fused2(const float* __restrict__ x,
          const float* __restrict__ rot,
          const float* __restrict__ ent,
          float* __restrict__ out,
          int n_threads) {
    __shared__ __align__(8) float2 sp2[72];
    int t = threadIdx.x;
    if (t < 72) {
        float v;
        if (t < 6)       v = -0.5f * rot[t * 3];
        else if (t < 12) v = __cosf(0.5f * rot[(t)      * 3]);   // layer1 c: (6+q)*3
        else if (t < 18) v = __sinf(0.5f * rot[(t - 6)  * 3]);   // layer1 s
        else if (t < 24) v = __sinf(-0.5f * rot[(t - 12)* 3]);   // layer1 -s
        else if (t < 30) v = __cosf(0.5f * rot[(t - 12) * 3]);   // layer2 c: (12+q)*3
        else if (t < 36) v = __sinf(0.5f * rot[(t - 18) * 3]);   // layer2 s
        else if (t < 42) v = __sinf(-0.5f * rot[(t - 24)* 3]);   // layer2 -s
        else if (t < 57) v = 0.5f / (1.0f + __expf(-ent[t - 42]));
        else { float tv = 0.5f / (1.0f + __expf(-ent[t - 57])); v = 1.0f - tv; }
        sp2[t] = make_float2(v, v);
    }
    __syncthreads();

    int tid = blockIdx.x * 256 + t;
    if (tid >= n_threads) return;

    const u64* P = reinterpret_cast<const u64*>(sp2);

    // 2 rows/thread = 12 floats = 3 float4 (rows at buf[0..5], buf[6..11]).
    const float4* xin = reinterpret_cast<const float4*>(x) + (size_t)tid * 3;
    float4* o4 = reinterpret_cast<float4*>(out) + (size_t)tid * 3;

    float4 va = __ldcs(xin + 0);
    float4 vb = __ldcs(xin + 1);
    float4 vc = __ldcs(xin + 2);
    float buf[12] = {va.x, va.y, va.z, va.w,
                     vb.x, vb.y, vb.z, vb.w,
                     vc.x, vc.y, vc.z, vc.w};

    const u64 PIH2 = pk2(PI_HALF, PI_HALF);

    u64 r[6], im[6];

    // init: h = x*pi/2 - th0 (packed fma), then scalar MUFU sincos per lane
#pragma unroll
    for (int q = 0; q < 6; q++) {
        u64 x2 = pk2(buf[q], buf[6 + q]);
        u64 h2 = fma2(x2, PIH2, P[P_NTH + q]);
        float h0, h1;
        upk2(h0, h1, h2);
        r[q]  = pk2(__cosf(h0), __cosf(h1));
        im[q] = pk2(__sinf(h0), __sinf(h1));
    }

    // 3 layers: (rotation for layers 1,2 — layer 0 folded) + entangle
#pragma unroll
    for (int layer = 0; layer < 3; layer++) {
        if (layer > 0) {
            int c  = (layer == 1) ? P_C1  : P_C2;
            int s  = (layer == 1) ? P_S1  : P_S2;
            int sn = (layer == 1) ? P_S1N : P_S2N;
#pragma unroll
            for (int q = 0; q < 6; q++) {
                u64 p1 = mul2(P[s + q],  im[q]);
                u64 nr = fma2(P[c + q],  r[q],  p1);
                u64 p2 = mul2(P[sn + q], r[q]);
                u64 ni = fma2(P[c + q],  im[q], p2);
                r[q] = nr; im[q] = ni;
            }
        }
        // entangle (snapshot semantics): n_q = (1-t_q)*r_q + t_q*r_{q+1};
        //                                n_5 = (1-t_4)*r_5 + t_4*r_4
        int tb = P_T + 5 * layer, ob = P_OMT + 5 * layer;
        u64 n0 = fma2(P[ob + 0], r[0], mul2(P[tb + 0], r[1]));
        u64 n1 = fma2(P[ob + 1], r[1], mul2(P[tb + 1], r[2]));
        u64 n2 = fma2(P[ob + 2], r[2], mul2(P[tb + 2], r[3]));
        u64 n3 = fma2(P[ob + 3], r[3], mul2(P[tb + 3], r[4]));
        u64 n4 = fma2(P[ob + 4], r[4], mul2(P[tb + 4], r[5]));
        u64 n5 = fma2(P[ob + 4], r[5], mul2(P[tb + 4], r[4]));
        r[0] = n0; r[1] = n1; r[2] = n2; r[3] = n3; r[4] = n4; r[5] = n5;
    }

    // magnitude: packed r^2 + im^2, scalar sqrt.approx per lane
#pragma unroll
    for (int q = 0; q < 6; q++) {
        u64 m2 = fma2(r[q], r[q], mul2(im[q], im[q]));
        float m0, m1;
        upk2(m0, m1, m2);
        buf[q]     = fsqrt_approx(m0);
        buf[6 + q] = fsqrt_approx(m1);
    }

    float4 oa = {buf[0], buf[1], buf[2],  buf[3]};
    float4 ob_ = {buf[4], buf[5], buf[6],  buf[7]};
    float4 oc = {buf[8], buf[9], buf[10], buf[11]};
    __stcs(o4 + 0, oa);
    __stcs(o4 + 1, ob_);
    __stcs(o4 + 2, oc);
}

extern "C" void kernel_launch(void* const* d_in, const int* in_sizes, int n_in,
                              void* d_out, int out_size) {
    const float* x   = (const float*)d_in[0];  // [BATCH, 6] fp32
    const float* rot = (const float*)d_in[1];  // [3, 6, 3]  fp32
    const float* ent = (const float*)d_in[2];  // [3, 5]     fp32
    float* out = (float*)d_out;                // [BATCH, 6] fp32

    int total_floats = in_sizes[0];            // BATCH * 6 (divisible by 12)
    int n_threads = total_floats / 12;         // 2 rows per thread
    int blocks = (n_threads + 255) / 256;
    qc_fused2<<<blocks, 256>>>(x, rot, ent, out, n_threads);
}

// round 12
// speedup vs baseline: 1.2022x; 1.2022x over previous
#include <cuda_runtime.h>

// QuantumCircuitLayer — fused scalar kernel, 1 row/thread, 32-reg / full-occupancy.
//   half = x*pi/2; r=cos(half), i=sin(half)
//   3x (per-qubit rotation, then nearest-neighbor real mixing); out = |state|
//
// R8 vs R3 (best 39.4us): revert f32x2 (R4 regression: LDS+MOV overhead),
// drop to 1 row/thread so the kernel fits 32 registers -> 64 warps/SM (100%
// occupancy, was 65%). IO via 3x LDG.64/STG.64 (24B row stride, 8B aligned).

#define PI_HALF 1.57079632679489662f

__device__ __forceinline__ float fsqrt_approx(float x) {
    float y;
    asm("sqrt.approx.f32 %0, %1;" : "=f"(y) : "f"(x));
    return y;
}

// Entangle, snapshot semantics: n_q = r_q + t_q*(r_{q+1}-r_q), q<5;
// n_5 = r_5 + t_4*(r_4 - r_5).   (t = sigmoid(ent)/2)
__device__ __forceinline__ void entangle(float r[6], const float* __restrict__ t) {
    float n0 = fmaf(t[0], r[1] - r[0], r[0]);
    float n1 = fmaf(t[1], r[2] - r[1], r[1]);
    float n2 = fmaf(t[2], r[3] - r[2], r[2]);
    float n3 = fmaf(t[3], r[4] - r[3], r[3]);
    float n4 = fmaf(t[4], r[5] - r[4], r[4]);
    float n5 = fmaf(t[4], r[4] - r[5], r[5]);
    r[0] = n0; r[1] = n1; r[2] = n2; r[3] = n3; r[4] = n4; r[5] = n5;
}

__global__ void __launch_bounds__(256, 8)
qc_fused(const float* __restrict__ x,
         const float* __restrict__ rot,
         const float* __restrict__ ent,
         float* __restrict__ out,
         int n_rows) {
    __shared__ float sp[48];
    // sp[ 0.. 5] = th0[q] = 0.5*rot[0,q,0]  (layer-0 rotation folded into phase)
    // sp[ 6..11] = c1[q]   sp[12..17] = s1[q]
    // sp[18..23] = c2[q]   sp[24..29] = s2[q]
    // sp[30..44] = 0.5*sigmoid(ent[l][j])   (3 layers x 5)
    int t = threadIdx.x;
    if (t < 48) {
        float v = 0.0f;
        if (t < 6)       v = 0.5f * rot[t * 3];
        else if (t < 12) v = __cosf(0.5f * rot[(t)      * 3]);  // layer1 c: (6+q)*3
        else if (t < 18) v = __sinf(0.5f * rot[(t - 6)  * 3]);  // layer1 s
        else if (t < 24) v = __cosf(0.5f * rot[(t - 6)  * 3]);  // layer2 c: (12+q)*3
        else if (t < 30) v = __sinf(0.5f * rot[(t - 12) * 3]);  // layer2 s
        else if (t < 45) v = 0.5f / (1.0f + __expf(-ent[t - 30]));
        sp[t] = v;
    }
    __syncthreads();

    int tid = blockIdx.x * 256 + t;
    if (tid >= n_rows) return;

    // One row per thread: 6 floats = 3 x float2 (24B stride -> 8B aligned).
    const float2* xin = reinterpret_cast<const float2*>(x) + (size_t)tid * 3;
    float2* o2 = reinterpret_cast<float2*>(out) + (size_t)tid * 3;

    float2 va = __ldcs(xin + 0);
    float2 vb = __ldcs(xin + 1);
    float2 vc = __ldcs(xin + 2);
    float xr[6] = {va.x, va.y, vb.x, vb.y, vc.x, vc.y};

    float r[6], im[6];

    // init with layer-0 rotation folded in: h = x*pi/2 - th0
#pragma unroll
    for (int q = 0; q < 6; q++) {
        float h = fmaf(xr[q], PI_HALF, -sp[q]);
        r[q]  = __cosf(h);
        im[q] = __sinf(h);
    }

    entangle(r, &sp[30]);          // layer 0 entangle

#pragma unroll
    for (int q = 0; q < 6; q++) {  // layer 1 rotation
        float c = sp[6 + q], s = sp[12 + q];
        float nr = fmaf(c, r[q],  s * im[q]);
        float ni = fmaf(c, im[q], -s * r[q]);
        r[q] = nr; im[q] = ni;
    }
    entangle(r, &sp[35]);          // layer 1 entangle

#pragma unroll
    for (int q = 0; q < 6; q++) {  // layer 2 rotation
        float c = sp[18 + q], s = sp[24 + q];
        float nr = fmaf(c, r[q],  s * im[q]);
        float ni = fmaf(c, im[q], -s * r[q]);
        r[q] = nr; im[q] = ni;
    }
    entangle(r, &sp[40]);          // layer 2 entangle

    // magnitude
#pragma unroll
    for (int q = 0; q < 6; q++)
        xr[q] = fsqrt_approx(fmaf(r[q], r[q], im[q] * im[q]));

    __stcs(o2 + 0, make_float2(xr[0], xr[1]));
    __stcs(o2 + 1, make_float2(xr[2], xr[3]));
    __stcs(o2 + 2, make_float2(xr[4], xr[5]));
}

extern "C" void kernel_launch(void* const* d_in, const int* in_sizes, int n_in,
                              void* d_out, int out_size) {
    const float* x   = (const float*)d_in[0];  // [BATCH, 6] fp32
    const float* rot = (const float*)d_in[1];  // [3, 6, 3]  fp32
    const float* ent = (const float*)d_in[2];  // [3, 5]     fp32
    float* out = (float*)d_out;                // [BATCH, 6] fp32

    int n_rows = in_sizes[0] / 6;              // BATCH
    int blocks = (n_rows + 255) / 256;
    qc_fused<<<blocks, 256>>>(x, rot, ent, out, n_rows);
}

// round 13
// speedup vs baseline: 1.3170x; 1.0955x over previous
#include <cuda_runtime.h>

// QuantumCircuitLayer — constant-bank params + 2 rows/thread float4 IO.
//
// R12 theory: previous plateau (~40us across 3 configs) was MIO/LSU-bound:
// ~45 LDS per thread for parameter reads (35% of the instruction stream,
// each a 29-cyc dep feeding an FMA). Fix: derived params go through
// __constant__ memory (precompute kernel -> __device__ scratch ->
// cudaMemcpyToSymbolAsync D2D -> LDCU/uniform-datapath reads, zero GPR,
// hoisted). Also 2 rows/thread via float4 halves LSU global instructions.

#define PI_HALF 1.57079632679489662f

// Constant param layout:
//  [ 0.. 5]  -th0[q] = -0.5*rot[0,q,0]   (layer-0 rotation folded into phase)
//  [ 6..11]  c1[q]   [12..17] s1[q]   [18..23] -s1[q]
//  [24..29]  c2[q]   [30..35] s2[q]   [36..41] -s2[q]
//  [42..56]  t[l,j]   = 0.5*sigmoid(ent[l,j])   (3 layers x 5)
//  [57..71]  1-t[l,j]
__constant__ float c_par[72];
__device__ float g_scratch[72];

__global__ void qc_precompute(const float* __restrict__ rot,
                              const float* __restrict__ ent) {
    int t = threadIdx.x;
    if (t >= 72) return;
    float v;
    if (t < 6)       v = -0.5f * rot[t * 3];
    else if (t < 12) v =  cosf(0.5f * rot[(t)      * 3]);   // l1 c: (6+q)*3, q=t-6
    else if (t < 18) v =  sinf(0.5f * rot[(t - 6)  * 3]);   // l1 s
    else if (t < 24) v = -sinf(0.5f * rot[(t - 12) * 3]);   // l1 -s
    else if (t < 30) v =  cosf(0.5f * rot[(t - 12) * 3]);   // l2 c: (12+q)*3, q=t-24
    else if (t < 36) v =  sinf(0.5f * rot[(t - 18) * 3]);   // l2 s
    else if (t < 42) v = -sinf(0.5f * rot[(t - 24) * 3]);   // l2 -s
    else if (t < 57) v = 0.5f / (1.0f + expf(-ent[t - 42]));
    else             v = 1.0f - 0.5f / (1.0f + expf(-ent[t - 57]));
    g_scratch[t] = v;
}

__device__ __forceinline__ float fsqrt_approx(float x) {
    float y;
    asm("sqrt.approx.f32 %0, %1;" : "=f"(y) : "f"(x));
    return y;
}

// One row: 6 inputs -> 6 outputs, all params from constant bank (UR-resident).
__device__ __forceinline__ void qc_row(const float xin[6], float xout[6]) {
    float r[6], im[6];

    // init with layer-0 rotation folded in: h = x*pi/2 - th0
#pragma unroll
    for (int q = 0; q < 6; q++) {
        float h = fmaf(xin[q], PI_HALF, c_par[q]);
        r[q]  = __cosf(h);
        im[q] = __sinf(h);
    }

#pragma unroll
    for (int layer = 0; layer < 3; layer++) {
        if (layer > 0) {
            int cb = (layer == 1) ? 6 : 24;   // c at cb, s at cb+6, -s at cb+12
#pragma unroll
            for (int q = 0; q < 6; q++) {
                float c = c_par[cb + q], s = c_par[cb + 6 + q], ns = c_par[cb + 12 + q];
                float nr = fmaf(c, r[q],  s  * im[q]);
                float ni = fmaf(c, im[q], ns * r[q]);
                r[q] = nr; im[q] = ni;
            }
        }
        // entangle, snapshot semantics: n_q = (1-t_q)*r_q + t_q*r_{q+1}, q<5
        //                               n_5 = (1-t_4)*r_5 + t_4*r_4
        int tb = 42 + 5 * layer, ob = 57 + 5 * layer;
        float n0 = fmaf(c_par[ob + 0], r[0], c_par[tb + 0] * r[1]);
        float n1 = fmaf(c_par[ob + 1], r[1], c_par[tb + 1] * r[2]);
        float n2 = fmaf(c_par[ob + 2], r[2], c_par[tb + 2] * r[3]);
        float n3 = fmaf(c_par[ob + 3], r[3], c_par[tb + 3] * r[4]);
        float n4 = fmaf(c_par[ob + 4], r[4], c_par[tb + 4] * r[5]);
        float n5 = fmaf(c_par[ob + 4], r[5], c_par[tb + 4] * r[4]);
        r[0] = n0; r[1] = n1; r[2] = n2; r[3] = n3; r[4] = n4; r[5] = n5;
    }

#pragma unroll
    for (int q = 0; q < 6; q++)
        xout[q] = fsqrt_approx(fmaf(r[q], r[q], im[q] * im[q]));
}

__global__ void __launch_bounds__(256, 6)
qc_main(const float* __restrict__ x, float* __restrict__ out, int n_threads) {
    int tid = blockIdx.x * 256 + threadIdx.x;
    if (tid >= n_threads) return;

    // 2 rows/thread = 12 floats = 3 float4 (48B stride, 16B aligned).
    const float4* xin = reinterpret_cast<const float4*>(x) + (size_t)tid * 3;
    float4* o4 = reinterpret_cast<float4*>(out) + (size_t)tid * 3;

    float4 va = __ldcs(xin + 0);
    float4 vb = __ldcs(xin + 1);
    float4 vc = __ldcs(xin + 2);

    float in0[6] = {va.x, va.y, va.z, va.w, vb.x, vb.y};
    float in1[6] = {vb.z, vb.w, vc.x, vc.y, vc.z, vc.w};
    float out0[6], out1[6];

    qc_row(in0, out0);
    qc_row(in1, out1);

    __stcs(o4 + 0, make_float4(out0[0], out0[1], out0[2], out0[3]));
    __stcs(o4 + 1, make_float4(out0[4], out0[5], out1[0], out1[1]));
    __stcs(o4 + 2, make_float4(out1[2], out1[3], out1[4], out1[5]));
}

extern "C" void kernel_launch(void* const* d_in, const int* in_sizes, int n_in,
                              void* d_out, int out_size) {
    const float* x   = (const float*)d_in[0];  // [BATCH, 6] fp32
    const float* rot = (const float*)d_in[1];  // [3, 6, 3]  fp32
    const float* ent = (const float*)d_in[2];  // [3, 5]     fp32
    float* out = (float*)d_out;                // [BATCH, 6] fp32

    qc_precompute<<<1, 96>>>(rot, ent);

    // D2D copy scratch -> constant bank (async, graph-capturable, no alloc).
    void* scratch_ptr = nullptr;
    cudaGetSymbolAddress(&scratch_ptr, g_scratch);
    cudaMemcpyToSymbolAsync(c_par, scratch_ptr, 72 * sizeof(float), 0,
                            cudaMemcpyDeviceToDevice, 0);

    int total_floats = in_sizes[0];            // BATCH * 6 (divisible by 12)
    int n_threads = total_floats / 12;         // 2 rows per thread
    int blocks = (n_threads + 255) / 256;
    qc_main<<<blocks, 256>>>(x, out, n_threads);
}